// round 14
// baseline (speedup 1.0000x reference)
#include <cuda_runtime.h>
#include <cstdint>

// Problem constants
#define ROWS   65536        // B*n = 8192*8
#define NE     1024         // codebook size
#define ED     64           // codebook dim
#define CHUNK  128          // codebook entries staged per iteration
#define NCHUNK (NE / CHUNK) // 8
#define RPB    64           // rows per block
#define TR     8            // rows per warp (8 warps * 8 = 64)
#define TE     4            // entries per lane per chunk (CHUNK/32)

// Output layout (tuple flattened, all float32) — validated R1-R13
#define OFF_LOSS  0
#define OFF_L1    1
#define OFF_L2    2
#define OFF_ZQST  3
#define OFF_ZOUT  4194307
#define OFF_PERP  8388611
#define OFF_OH    8388612
#define OFF_IDX   75497476

__device__ int    g_hist[NE];
__device__ double g_loss;
__device__ float  g_wsum[NE];

__device__ __forceinline__ void ffma2(unsigned long long &acc,
                                      unsigned long long a,
                                      unsigned long long b) {
    asm("fma.rn.f32x2 %0, %1, %2, %0;" : "+l"(acc) : "l"(a), "l"(b));
}
__device__ __forceinline__ float2 unpack2(unsigned long long v) {
    float2 r;
    asm("mov.b64 {%0, %1}, %2;" : "=f"(r.x), "=f"(r.y) : "l"(v));
    return r;
}

// ---------------------------------------------------------------------------
// prep: per-entry ||w||^2, zero histogram + loss accumulator
// ---------------------------------------------------------------------------
__global__ void vq_prep(const float* __restrict__ w) {
    int e = blockIdx.x, lane = threadIdx.x;
    const float* wr = w + e * ED;
    float a = wr[lane], b = wr[lane + 32];
    float s = a * a + b * b;
    #pragma unroll
    for (int o = 16; o; o >>= 1) s += __shfl_down_sync(0xffffffffu, s, o);
    if (lane == 0) {
        g_wsum[e] = s;
        g_hist[e] = 0;
        if (e == 0) g_loss = 0.0;
    }
}

// ---------------------------------------------------------------------------
// main kernel — exact R4 engine (geometry, staging, swizzle, epilogue) plus:
//  * z via LDS.128 uniform broadcasts covering 2 dps (crossbar 16->12
//    wavefronts per 32 warp-FFMA2)
//  * software-pipelined w loads: double-buffered wv, prefetch dp+1 while
//    FMA-ing dp (wrap on last dp -> dead load, no branch). Load reordering
//    only; FMA accumulation order is bit-identical to R4.
// One-hot zeros fire-and-forget in the chunk loop; 1.0 after block fence.
// Scores: (||z||^2 + ||w||^2) - 2*dot, fp32, dp-ascending (= R4).
// ---------------------------------------------------------------------------
__global__ __launch_bounds__(256) void vq_argmin(
    const float* __restrict__ z, const float* __restrict__ w,
    float* __restrict__ out)
{
    __shared__ float  zs[RPB * ED];       // 16384 B: z tile (row-major)
    __shared__ float2 wp[32 * CHUNK];     // 32768 B: w chunk [dpair][entry] swizzled

    const int tid = threadIdx.x, lane = tid & 31, warp = tid >> 5;
    const int rowBase = blockIdx.x * RPB;
    const int myRow0 = warp * TR;

    // stage z tile (coalesced float4)
    {
        const float4* zg = (const float4*)(z + (size_t)rowBase * ED);
        float4* zt = (float4*)zs;
        #pragma unroll
        for (int i = tid; i < RPB * ED / 4; i += 256) zt[i] = zg[i];
    }
    __syncthreads();

    // per-warp zsum: lane r (<8) owns row myRow0+r, sequential d-order (= R4)
    float myzsum = 0.f;
    if (lane < TR) {
        const float* zr = zs + (myRow0 + lane) * ED;
        #pragma unroll
        for (int d = 0; d < ED; d++) myzsum += zr[d] * zr[d];
    }

    float best[TR]; int bidx[TR];
    #pragma unroll
    for (int r = 0; r < TR; r++) { best[r] = 3.402823e38f; bidx[r] = 0x7fffffff; }

    const unsigned long long* zs2 = (const unsigned long long*)zs;  // 32 ull/row
    float4* ohp = (float4*)(out + OFF_OH + (size_t)rowBase * NE);
    const float4 zero4 = make_float4(0.f, 0.f, 0.f, 0.f);

    for (int c = 0; c < NE; c += CHUNK) {
        __syncthreads();   // protect wp reuse
        // stage w chunk as [dpair][entry] with xor-swizzle (R4-validated:
        // coalesced float2 reads, conflict-free stores)
        {
            const float2* wg = (const float2*)(w + (size_t)c * ED);
            #pragma unroll
            for (int i = tid; i < CHUNK * 32; i += 256) {
                int e = i >> 5, dp = i & 31;
                int col = (e & ~31) | ((e & 31) ^ dp);
                wp[dp * CHUNK + col] = wg[i];
            }
        }
        __syncthreads();

        // fire-and-forget: zero 1/NCHUNK of this block's one-hot slice
        {
            int it = c / CHUNK;                    // 0..7
            #pragma unroll
            for (int k = 0; k < (RPB * NE / 4) / (NCHUNK * 256); k++)
                ohp[it * (RPB * NE / 4 / NCHUNK) + k * 256 + tid] = zero4;
        }

        unsigned long long acc[TR][TE];
        #pragma unroll
        for (int r = 0; r < TR; r++)
            #pragma unroll
            for (int j = 0; j < TE; j++) acc[r][j] = 0ull;

        // prime the w pipeline with dp=0
        unsigned long long wv_cur[TE], wv_nxt[TE];
        #pragma unroll
        for (int j = 0; j < TE; j++)
            wv_cur[j] = *(const unsigned long long*)&wp[0 * CHUNK + ((j << 5) | lane)];

        #pragma unroll 4
        for (int dp2 = 0; dp2 < 16; dp2++) {
            // z: one LDS.128 uniform broadcast covers dps (2*dp2, 2*dp2+1)
            ulonglong2 zv2[TR];
            #pragma unroll
            for (int r = 0; r < TR; r++)
                zv2[r] = *(const ulonglong2*)&zs2[(myRow0 + r) * 32 + 2 * dp2];
            #pragma unroll
            for (int h = 0; h < 2; h++) {
                const int dp = 2 * dp2 + h;
                const int dpn = (dp + 1) & 31;     // wrap: last prefetch is dead
                #pragma unroll
                for (int j = 0; j < TE; j++) {
                    int col = (j << 5) | (lane ^ dpn);
                    wv_nxt[j] = *(const unsigned long long*)&wp[dpn * CHUNK + col];
                }
                #pragma unroll
                for (int r = 0; r < TR; r++) {
                    unsigned long long zv = h ? zv2[r].y : zv2[r].x;
                    #pragma unroll
                    for (int j = 0; j < TE; j++)
                        ffma2(acc[r][j], zv, wv_cur[j]);
                }
                #pragma unroll
                for (int j = 0; j < TE; j++) wv_cur[j] = wv_nxt[j];
            }
        }

        #pragma unroll
        for (int r = 0; r < TR; r++) {
            float zsr = __shfl_sync(0xffffffffu, myzsum, r);
            #pragma unroll
            for (int j = 0; j < TE; j++) {
                float2 a = unpack2(acc[r][j]);
                float dot = a.x + a.y;
                int e = c + (j << 5) + lane;
                float t = zsr + g_wsum[e];
                float s = t - 2.0f * dot;      // matches reference fp32 ordering
                if (s < best[r] || (s == best[r] && e < bidx[r])) {
                    best[r] = s; bidx[r] = e;
                }
            }
        }
    }

    __syncthreads();   // fence: all one-hot zeros precede the 1.0 stores below

    // per-row warp reduction + epilogue
    double dacc = 0.0;
    #pragma unroll
    for (int r = 0; r < TR; r++) {
        float v = best[r]; int id = bidx[r];
        #pragma unroll
        for (int o = 16; o; o >>= 1) {
            float v2 = __shfl_down_sync(0xffffffffu, v, o);
            int   i2 = __shfl_down_sync(0xffffffffu, id, o);
            if (v2 < v || (v2 == v && i2 < id)) { v = v2; id = i2; }
        }
        id = __shfl_sync(0xffffffffu, id, 0);

        int grow = rowBase + myRow0 + r;
        const float* wrow = w + (size_t)id * ED;
        float dsq = 0.f;
        #pragma unroll
        for (int d = lane; d < ED; d += 32) {
            float zq = wrow[d];                  // z_q = exact codebook row
            float zr = zs[(myRow0 + r) * ED + d];
            float df = zq - zr;
            float st = zr + df;                  // straight-through fp32 replay
            out[OFF_ZQST + (size_t)grow * ED + d] = st;
            out[OFF_ZOUT + (size_t)grow * ED + d] = st;
            dsq += df * df;
        }
        #pragma unroll
        for (int o = 16; o; o >>= 1) dsq += __shfl_down_sync(0xffffffffu, dsq, o);
        if (lane == 0) {
            atomicAdd(&g_hist[id], 1);
            out[OFF_IDX + grow] = (float)id;
            out[OFF_OH + (size_t)grow * NE + id] = 1.0f;   // after fenced zeros
            dacc += (double)dsq;
        }
    }
    if (lane == 0 && dacc != 0.0) atomicAdd(&g_loss, dacc);
}

// ---------------------------------------------------------------------------
// finalize: losses + perplexity scalars
// ---------------------------------------------------------------------------
__global__ void vq_finalize(float* __restrict__ out) {
    __shared__ float red[1024];
    int t = threadIdx.x;
    float p = (float)g_hist[t] / 65536.0f;
    red[t] = p * logf(p + 1e-10f);
    __syncthreads();
    #pragma unroll
    for (int s = 512; s; s >>= 1) {
        if (t < s) red[t] += red[t + s];
        __syncthreads();
    }
    if (t == 0) {
        out[OFF_PERP] = expf(-red[0]);
        float l1 = (float)(g_loss / 4194304.0);
        out[OFF_L1] = l1;
        out[OFF_L2] = l1;                 // loss2 == loss1 numerically
        out[OFF_LOSS] = l1 + 0.25f * l1;  // GAMMA*l1 + BETA*l2
    }
}

// ---------------------------------------------------------------------------
extern "C" void kernel_launch(void* const* d_in, const int* in_sizes, int n_in,
                              void* d_out, int out_size)
{
    const float* z = (const float*)d_in[0];   // (8192, 512)
    const float* w = (const float*)d_in[1];   // (1024, 64)
    float* out = (float*)d_out;

    vq_prep<<<NE, 32>>>(w);
    vq_argmin<<<ROWS / RPB, 256>>>(z, w, out);
    vq_finalize<<<1, 1024>>>(out);
}

// round 15
// speedup vs baseline: 1.0107x; 1.0107x over previous
#include <cuda_runtime.h>
#include <cstdint>

// Problem constants
#define ROWS   65536        // B*n = 8192*8
#define NE     1024         // codebook size
#define ED     64           // codebook dim
#define CHUNK  256          // codebook entries staged per iteration
#define NCHUNK (NE / CHUNK) // 4
#define RPB    64           // rows per block
#define TR     8            // rows per warp (8 warps * 8 = 64)
#define TE     8            // entry-ull per lane per chunk (CHUNK/32)

// Output layout (tuple flattened, all float32) — validated R1-R14
#define OFF_LOSS  0
#define OFF_L1    1
#define OFF_L2    2
#define OFF_ZQST  3
#define OFF_ZOUT  4194307
#define OFF_PERP  8388611
#define OFF_OH    8388612
#define OFF_IDX   75497476

// dynamic smem partition (bytes)
#define S_ZS   0                      // 16384 B: z tile
#define S_WP   16384                  // 65536 B: w chunk [dp][entry] swizzled
#define S_TOT  (16384 + 65536)        // 81920 B

__device__ int    g_hist[NE];
__device__ double g_loss;
__device__ float  g_wsum[NE];

__device__ __forceinline__ void ffma2(unsigned long long &acc,
                                      unsigned long long a,
                                      unsigned long long b) {
    asm("fma.rn.f32x2 %0, %1, %2, %0;" : "+l"(acc) : "l"(a), "l"(b));
}
__device__ __forceinline__ float2 unpack2(unsigned long long v) {
    float2 r;
    asm("mov.b64 {%0, %1}, %2;" : "=f"(r.x), "=f"(r.y) : "l"(v));
    return r;
}

// ---------------------------------------------------------------------------
// prep: per-entry ||w||^2, zero histogram + loss accumulator
// ---------------------------------------------------------------------------
__global__ void vq_prep(const float* __restrict__ w) {
    int e = blockIdx.x, lane = threadIdx.x;
    const float* wr = w + e * ED;
    float a = wr[lane], b = wr[lane + 32];
    float s = a * a + b * b;
    #pragma unroll
    for (int o = 16; o; o >>= 1) s += __shfl_down_sync(0xffffffffu, s, o);
    if (lane == 0) {
        g_wsum[e] = s;
        g_hist[e] = 0;
        if (e == 0) g_loss = 0.0;
    }
}

// ---------------------------------------------------------------------------
// main kernel — EXACT R4 inner-loop structure (LDS.64 z broadcasts, xor-
// swizzled w, no prefetch), with the register-blocking widened: TE 4->8
// (16 entries/lane/chunk, CHUNK=256). Per warp per dp: 64 FFMA2 from
// 24 load-wavefronts (2.67 FFMA2/wf vs R4's 2.0); crossbar ratio 0.375.
// 4 chunks instead of 8 -> half the barriers/staging passes.
// acc=128 regs, total ~185 -> 1 block/SM (same occupancy as R4).
// One-hot zeros fire-and-forget in the chunk loop; 1.0 after block fence.
// Scores bit-identical to R4: (||z||^2+||w||^2) - 2*dot, fp32, dp-ascending.
// ---------------------------------------------------------------------------
__global__ __launch_bounds__(256) void vq_argmin(
    const float* __restrict__ z, const float* __restrict__ w,
    float* __restrict__ out)
{
    extern __shared__ char smem[];
    float*  zs = (float*)(smem + S_ZS);    // 64 rows x 64 dims
    float2* wp = (float2*)(smem + S_WP);   // [dp][entry] swizzled, 32 x 256

    const int tid = threadIdx.x, lane = tid & 31, warp = tid >> 5;
    const int rowBase = blockIdx.x * RPB;
    const int myRow0 = warp * TR;

    // stage z tile (coalesced float4)
    {
        const float4* zg = (const float4*)(z + (size_t)rowBase * ED);
        float4* zt = (float4*)zs;
        #pragma unroll
        for (int i = tid; i < RPB * ED / 4; i += 256) zt[i] = zg[i];
    }
    __syncthreads();

    // per-warp zsum: lane r (<8) owns row myRow0+r, sequential d-order (= R4)
    float myzsum = 0.f;
    if (lane < TR) {
        const float* zr = zs + (myRow0 + lane) * ED;
        #pragma unroll
        for (int d = 0; d < ED; d++) myzsum += zr[d] * zr[d];
    }

    float best[TR]; int bidx[TR];
    #pragma unroll
    for (int r = 0; r < TR; r++) { best[r] = 3.402823e38f; bidx[r] = 0x7fffffff; }

    const unsigned long long* zs2 = (const unsigned long long*)zs;  // 32 ull/row
    float4* ohp = (float4*)(out + OFF_OH + (size_t)rowBase * NE);
    const float4 zero4 = make_float4(0.f, 0.f, 0.f, 0.f);

    for (int c = 0; c < NE; c += CHUNK) {
        __syncthreads();   // protect wp reuse
        // stage w chunk as [dp][entry] with xor-swizzle (R4-validated pattern)
        {
            const float2* wg = (const float2*)(w + (size_t)c * ED);
            #pragma unroll
            for (int i = tid; i < CHUNK * 32; i += 256) {
                int e = i >> 5, dp = i & 31;
                int col = (e & ~31) | ((e & 31) ^ dp);
                wp[dp * CHUNK + col] = wg[i];
            }
        }
        __syncthreads();

        // fire-and-forget: zero 1/NCHUNK of this block's one-hot slice
        {
            int it = c / CHUNK;                    // 0..3
            #pragma unroll
            for (int k = 0; k < (RPB * NE / 4) / (NCHUNK * 256); k++)
                ohp[it * (RPB * NE / 4 / NCHUNK) + k * 256 + tid] = zero4;
        }

        unsigned long long acc[TR][TE];
        #pragma unroll
        for (int r = 0; r < TR; r++)
            #pragma unroll
            for (int j = 0; j < TE; j++) acc[r][j] = 0ull;

        #pragma unroll 4
        for (int dp = 0; dp < 32; dp++) {
            unsigned long long zv[TR], wv[TE];
            #pragma unroll
            for (int r = 0; r < TR; r++)
                zv[r] = zs2[(myRow0 + r) * 32 + dp];          // uniform broadcast
            #pragma unroll
            for (int j = 0; j < TE; j++) {
                int col = (j << 5) | (lane ^ dp);
                wv[j] = *(const unsigned long long*)&wp[dp * CHUNK + col];
            }
            #pragma unroll
            for (int r = 0; r < TR; r++)
                #pragma unroll
                for (int j = 0; j < TE; j++)
                    ffma2(acc[r][j], zv[r], wv[j]);
        }

        #pragma unroll
        for (int r = 0; r < TR; r++) {
            float zsr = __shfl_sync(0xffffffffu, myzsum, r);
            #pragma unroll
            for (int j = 0; j < TE; j++) {
                float2 a = unpack2(acc[r][j]);
                float dot = a.x + a.y;
                int e = c + (j << 5) + lane;
                float t = zsr + g_wsum[e];
                float s = t - 2.0f * dot;      // matches reference fp32 ordering
                if (s < best[r] || (s == best[r] && e < bidx[r])) {
                    best[r] = s; bidx[r] = e;
                }
            }
        }
    }

    __syncthreads();   // fence: all one-hot zeros precede the 1.0 stores below

    // per-row warp reduction + epilogue
    double dacc = 0.0;
    #pragma unroll
    for (int r = 0; r < TR; r++) {
        float v = best[r]; int id = bidx[r];
        #pragma unroll
        for (int o = 16; o; o >>= 1) {
            float v2 = __shfl_down_sync(0xffffffffu, v, o);
            int   i2 = __shfl_down_sync(0xffffffffu, id, o);
            if (v2 < v || (v2 == v && i2 < id)) { v = v2; id = i2; }
        }
        id = __shfl_sync(0xffffffffu, id, 0);

        int grow = rowBase + myRow0 + r;
        const float* wrow = w + (size_t)id * ED;
        float dsq = 0.f;
        #pragma unroll
        for (int d = lane; d < ED; d += 32) {
            float zq = wrow[d];                  // z_q = exact codebook row
            float zr = zs[(myRow0 + r) * ED + d];
            float df = zq - zr;
            float st = zr + df;                  // straight-through fp32 replay
            out[OFF_ZQST + (size_t)grow * ED + d] = st;
            out[OFF_ZOUT + (size_t)grow * ED + d] = st;
            dsq += df * df;
        }
        #pragma unroll
        for (int o = 16; o; o >>= 1) dsq += __shfl_down_sync(0xffffffffu, dsq, o);
        if (lane == 0) {
            atomicAdd(&g_hist[id], 1);
            out[OFF_IDX + grow] = (float)id;
            out[OFF_OH + (size_t)grow * NE + id] = 1.0f;   // after fenced zeros
            dacc += (double)dsq;
        }
    }
    if (lane == 0 && dacc != 0.0) atomicAdd(&g_loss, dacc);
}

// ---------------------------------------------------------------------------
// finalize: losses + perplexity scalars
// ---------------------------------------------------------------------------
__global__ void vq_finalize(float* __restrict__ out) {
    __shared__ float red[1024];
    int t = threadIdx.x;
    float p = (float)g_hist[t] / 65536.0f;
    red[t] = p * logf(p + 1e-10f);
    __syncthreads();
    #pragma unroll
    for (int s = 512; s; s >>= 1) {
        if (t < s) red[t] += red[t + s];
        __syncthreads();
    }
    if (t == 0) {
        out[OFF_PERP] = expf(-red[0]);
        float l1 = (float)(g_loss / 4194304.0);
        out[OFF_L1] = l1;
        out[OFF_L2] = l1;                 // loss2 == loss1 numerically
        out[OFF_LOSS] = l1 + 0.25f * l1;  // GAMMA*l1 + BETA*l2
    }
}

// ---------------------------------------------------------------------------
extern "C" void kernel_launch(void* const* d_in, const int* in_sizes, int n_in,
                              void* d_out, int out_size)
{
    const float* z = (const float*)d_in[0];   // (8192, 512)
    const float* w = (const float*)d_in[1];   // (1024, 64)
    float* out = (float*)d_out;

    cudaFuncSetAttribute(vq_argmin, cudaFuncAttributeMaxDynamicSharedMemorySize,
                         S_TOT);

    vq_prep<<<NE, 32>>>(w);
    vq_argmin<<<ROWS / RPB, 256, S_TOT>>>(z, w, out);
    vq_finalize<<<1, 1024>>>(out);
}

// round 16
// speedup vs baseline: 1.2109x; 1.1981x over previous
#include <cuda_runtime.h>
#include <cstdint>

// Problem constants
#define ROWS   65536        // B*n = 8192*8
#define NE     1024         // codebook size
#define ED     64           // codebook dim
#define CHUNK  128          // codebook entries staged per iteration
#define NCHUNK (NE / CHUNK) // 8
#define RPB    64           // rows per block
#define TR     8            // rows per warp (8 warps * 8 = 64)
#define TE     4            // entries per lane per chunk (CHUNK/32)

// Output layout (tuple flattened, all float32) — validated R1/R2
#define OFF_LOSS  0
#define OFF_L1    1
#define OFF_L2    2
#define OFF_ZQST  3
#define OFF_ZOUT  4194307
#define OFF_PERP  8388611
#define OFF_OH    8388612
#define OFF_IDX   75497476

__device__ int    g_hist[NE];
__device__ double g_loss;
__device__ float  g_wsum[NE];

__device__ __forceinline__ void ffma2(unsigned long long &acc,
                                      unsigned long long a,
                                      unsigned long long b) {
    asm("fma.rn.f32x2 %0, %1, %2, %0;" : "+l"(acc) : "l"(a), "l"(b));
}
__device__ __forceinline__ float2 unpack2(unsigned long long v) {
    float2 r;
    asm("mov.b64 {%0, %1}, %2;" : "=f"(r.x), "=f"(r.y) : "l"(v));
    return r;
}

// ---------------------------------------------------------------------------
// prep: per-entry ||w||^2, zero histogram + loss accumulator
// ---------------------------------------------------------------------------
__global__ void vq_prep(const float* __restrict__ w) {
    int e = blockIdx.x, lane = threadIdx.x;
    const float* wr = w + e * ED;
    float a = wr[lane], b = wr[lane + 32];
    float s = a * a + b * b;
    #pragma unroll
    for (int o = 16; o; o >>= 1) s += __shfl_down_sync(0xffffffffu, s, o);
    if (lane == 0) {
        g_wsum[e] = s;
        g_hist[e] = 0;
        if (e == 0) g_loss = 0.0;
    }
}

// ---------------------------------------------------------------------------
// main kernel: fused distance-GEMM + row argmin + one-hot + z_q epilogue.
// Block: 64 rows. Warp: 8 rows (broadcast from smem). Lane: 4 entries/chunk.
// zsum lives in registers (lane r<8 owns row myRow0+r, sequential d-order),
// fetched by shuffle -> smem is exactly 49152 B (the 0xc000 static limit).
// One-hot zeros written fire-and-forget inside the chunk loop; the 1.0 is
// ordered after them by the post-loop __syncthreads (block fence).
// Scores computed exactly as R1: (||z||^2 + ||w||^2) - 2*dot, fp32.
// ---------------------------------------------------------------------------
__global__ __launch_bounds__(256) void vq_argmin(
    const float* __restrict__ z, const float* __restrict__ w,
    float* __restrict__ out)
{
    __shared__ float  zs[RPB * ED];       // 16384 B: z tile (row-major)
    __shared__ float2 wp[32 * CHUNK];     // 32768 B: w chunk [dpair][entry] swizzled

    const int tid = threadIdx.x, lane = tid & 31, warp = tid >> 5;
    const int rowBase = blockIdx.x * RPB;
    const int myRow0 = warp * TR;

    // stage z tile (coalesced float4)
    {
        const float4* zg = (const float4*)(z + (size_t)rowBase * ED);
        float4* zt = (float4*)zs;
        #pragma unroll
        for (int i = tid; i < RPB * ED / 4; i += 256) zt[i] = zg[i];
    }
    __syncthreads();

    // per-warp zsum: lane r (<8) owns row myRow0+r, sequential order (= R1)
    float myzsum = 0.f;
    if (lane < TR) {
        const float* zr = zs + (myRow0 + lane) * ED;
        #pragma unroll
        for (int d = 0; d < ED; d++) myzsum += zr[d] * zr[d];
    }

    float best[TR]; int bidx[TR];
    #pragma unroll
    for (int r = 0; r < TR; r++) { best[r] = 3.402823e38f; bidx[r] = 0x7fffffff; }

    const float2* zs2 = (const float2*)zs;
    float4* ohp = (float4*)(out + OFF_OH + (size_t)rowBase * NE);
    const float4 zero4 = make_float4(0.f, 0.f, 0.f, 0.f);

    for (int c = 0; c < NE; c += CHUNK) {
        __syncthreads();   // protect wp reuse
        // stage w chunk as [dpair][entry] with xor-swizzle (conflict-free LDS)
        {
            const float2* wg = (const float2*)(w + (size_t)c * ED);
            #pragma unroll
            for (int i = tid; i < CHUNK * 32; i += 256) {
                int e = i >> 5, dp = i & 31;
                int col = (e & ~31) | ((e & 31) ^ dp);
                wp[dp * CHUNK + col] = wg[i];
            }
        }
        __syncthreads();

        // fire-and-forget: zero 1/NCHUNK of this block's one-hot slice
        {
            int it = c / CHUNK;                    // 0..7
            #pragma unroll
            for (int k = 0; k < (RPB * NE / 4) / (NCHUNK * 256); k++)
                ohp[it * (RPB * NE / 4 / NCHUNK) + k * 256 + tid] = zero4;
        }

        unsigned long long acc[TR][TE];
        #pragma unroll
        for (int r = 0; r < TR; r++)
            #pragma unroll
            for (int j = 0; j < TE; j++) acc[r][j] = 0ull;

        #pragma unroll 8
        for (int dp = 0; dp < 32; dp++) {
            unsigned long long zv[TR], wv[TE];
            #pragma unroll
            for (int r = 0; r < TR; r++)
                zv[r] = *(const unsigned long long*)&zs2[(myRow0 + r) * 32 + dp];
            #pragma unroll
            for (int j = 0; j < TE; j++) {
                int col = (j << 5) | (lane ^ dp);
                wv[j] = *(const unsigned long long*)&wp[dp * CHUNK + col];
            }
            #pragma unroll
            for (int r = 0; r < TR; r++)
                #pragma unroll
                for (int j = 0; j < TE; j++)
                    ffma2(acc[r][j], zv[r], wv[j]);
        }

        #pragma unroll
        for (int r = 0; r < TR; r++) {
            float zsr = __shfl_sync(0xffffffffu, myzsum, r);
            #pragma unroll
            for (int j = 0; j < TE; j++) {
                float2 a = unpack2(acc[r][j]);
                float dot = a.x + a.y;
                int e = c + (j << 5) + lane;
                float t = zsr + g_wsum[e];
                float s = t - 2.0f * dot;      // matches reference fp32 ordering
                if (s < best[r] || (s == best[r] && e < bidx[r])) {
                    best[r] = s; bidx[r] = e;
                }
            }
        }
    }

    __syncthreads();   // fence: all one-hot zeros precede the 1.0 stores below

    // per-row warp reduction + epilogue
    double dacc = 0.0;
    #pragma unroll
    for (int r = 0; r < TR; r++) {
        float v = best[r]; int id = bidx[r];
        #pragma unroll
        for (int o = 16; o; o >>= 1) {
            float v2 = __shfl_down_sync(0xffffffffu, v, o);
            int   i2 = __shfl_down_sync(0xffffffffu, id, o);
            if (v2 < v || (v2 == v && i2 < id)) { v = v2; id = i2; }
        }
        id = __shfl_sync(0xffffffffu, id, 0);

        int grow = rowBase + myRow0 + r;
        const float* wrow = w + (size_t)id * ED;
        float dsq = 0.f;
        #pragma unroll
        for (int d = lane; d < ED; d += 32) {
            float zq = wrow[d];                  // z_q = exact codebook row
            float zr = zs[(myRow0 + r) * ED + d];
            float df = zq - zr;
            float st = zr + df;                  // straight-through fp32 replay
            out[OFF_ZQST + (size_t)grow * ED + d] = st;
            out[OFF_ZOUT + (size_t)grow * ED + d] = st;
            dsq += df * df;
        }
        #pragma unroll
        for (int o = 16; o; o >>= 1) dsq += __shfl_down_sync(0xffffffffu, dsq, o);
        if (lane == 0) {
            atomicAdd(&g_hist[id], 1);
            out[OFF_IDX + grow] = (float)id;
            out[OFF_OH + (size_t)grow * NE + id] = 1.0f;   // after fenced zeros
            dacc += (double)dsq;
        }
    }
    if (lane == 0 && dacc != 0.0) atomicAdd(&g_loss, dacc);
}

// ---------------------------------------------------------------------------
// finalize: losses + perplexity scalars
// ---------------------------------------------------------------------------
__global__ void vq_finalize(float* __restrict__ out) {
    __shared__ float red[1024];
    int t = threadIdx.x;
    float p = (float)g_hist[t] / 65536.0f;
    red[t] = p * logf(p + 1e-10f);
    __syncthreads();
    #pragma unroll
    for (int s = 512; s; s >>= 1) {
        if (t < s) red[t] += red[t + s];
        __syncthreads();
    }
    if (t == 0) {
        out[OFF_PERP] = expf(-red[0]);
        float l1 = (float)(g_loss / 4194304.0);
        out[OFF_L1] = l1;
        out[OFF_L2] = l1;                 // loss2 == loss1 numerically
        out[OFF_LOSS] = l1 + 0.25f * l1;  // GAMMA*l1 + BETA*l2
    }
}

// ---------------------------------------------------------------------------
extern "C" void kernel_launch(void* const* d_in, const int* in_sizes, int n_in,
                              void* d_out, int out_size)
{
    const float* z = (const float*)d_in[0];   // (8192, 512)
    const float* w = (const float*)d_in[1];   // (1024, 64)
    float* out = (float*)d_out;

    vq_prep<<<NE, 32>>>(w);
    vq_argmin<<<ROWS / RPB, 256>>>(z, w, out);
    vq_finalize<<<1, 1024>>>(out);
}